// round 2
// baseline (speedup 1.0000x reference)
#include <cuda_runtime.h>
#include <math.h>

#define NN 10000
#define NE 320000
#define FIN 512
#define HIDC 256
#define ZC 64
#define NH 8
#define ND0 32
#define ND1 8
#define NEG_SLOPE 0.2f

typedef unsigned long long ull;

// ---------------- packed f32x2 helpers (Blackwell) ----------------
__device__ __forceinline__ void fma2(ull& d, ull a, ull b) {
    asm("fma.rn.f32x2 %0, %1, %2, %0;" : "+l"(d) : "l"(a), "l"(b));
}
__device__ __forceinline__ ull pack2(float x) {
    ull r; asm("mov.b64 %0, {%1, %1};" : "=l"(r) : "f"(x)); return r;
}
__device__ __forceinline__ float2 unpack2(ull v) {
    float2 r; asm("mov.b64 {%0, %1}, %2;" : "=f"(r.x), "=f"(r.y) : "l"(v)); return r;
}

// ---------------- scratch (static device memory; no allocations) ----------------
__device__ float g_lin0[NN * HIDC];
__device__ float g_gat0[NN * HIDC];
__device__ float g_lin1[NN * ZC];
__device__ float g_lin2[NN * ZC];
__device__ float g_mean[NN * ZC];
__device__ float g_lstd[NN * ZC];
__device__ float g_el[NN * NH];
__device__ float g_er[NN * NH];
__device__ float g_el2[NN * NH];
__device__ float g_er2[NN * NH];
__device__ float g_e[NE * NH];        // per-edge scratch, SORTED edge order
__device__ int   g_deg[NN];
__device__ int   g_off[NN + 1];
__device__ int   g_cur[NN];
__device__ int   g_ssrc[NE];          // src per sorted edge

// ---------------- counting sort of edges by dst ----------------
__global__ void k_zero_deg() {
    int i = blockIdx.x * blockDim.x + threadIdx.x;
    if (i < NN) g_deg[i] = 0;
}

__global__ void k_hist(const int* __restrict__ dst) {
    int i = blockIdx.x * blockDim.x + threadIdx.x;
    if (i < NE) atomicAdd(&g_deg[dst[i]], 1);
}

__global__ void k_scan() {
    const int CH = 10;
    __shared__ int sh[1024];
    int t = threadIdx.x;
    int base = t * CH;
    int vals[CH];
    int loc = 0;
#pragma unroll
    for (int i = 0; i < CH; i++) {
        int idx = base + i;
        vals[i] = (idx < NN) ? g_deg[idx] : 0;
        loc += vals[i];
    }
    sh[t] = loc;
    __syncthreads();
    for (int off = 1; off < 1024; off <<= 1) {
        int v = (t >= off) ? sh[t - off] : 0;
        __syncthreads();
        sh[t] += v;
        __syncthreads();
    }
    int run = sh[t] - loc;
#pragma unroll
    for (int i = 0; i < CH; i++) {
        int idx = base + i;
        if (idx < NN) {
            g_off[idx] = run;
            g_cur[idx] = run;
            run += vals[i];
        }
    }
    if (t == 0) g_off[NN] = NE;
}

__global__ void k_scatter(const int* __restrict__ src, const int* __restrict__ dst) {
    int e = blockIdx.x * blockDim.x + threadIdx.x;
    if (e < NE) {
        int d = dst[e];
        int pos = atomicAdd(&g_cur[d], 1);
        g_ssrc[pos] = src[e];
    }
}

// ---------------- fp32 tiled GEMM with f32x2 FMAs ----------------
__global__ __launch_bounds__(256) void k_sgemm(const float* __restrict__ A,
                                               const float* __restrict__ B,
                                               float* __restrict__ C,
                                               int M, int K, int Nn) {
    __shared__ float As[64 * 32];   // [row][k]
    __shared__ float Bs[32 * 64];   // [k][col]
    int tid = threadIdx.x;
    int tx = tid & 15, ty = tid >> 4;
    int rowBase = blockIdx.y * 64;
    int colBase = blockIdx.x * 64;
    ull acc[4][2] = {};

    for (int kb = 0; kb < K; kb += 32) {
        {
            int r = tid >> 3;
            int c = (tid & 7) << 2;
#pragma unroll
            for (int p = 0; p < 2; p++) {
                int rr = r + p * 32;
                int grow = rowBase + rr;
                float4 v = make_float4(0.f, 0.f, 0.f, 0.f);
                if (grow < M) v = *(const float4*)(A + (size_t)grow * K + kb + c);
                *(float4*)(As + rr * 32 + c) = v;
            }
            int r2 = tid >> 4;
            int c2 = (tid & 15) << 2;
#pragma unroll
            for (int p = 0; p < 2; p++) {
                int rr = r2 + p * 16;
                float4 v = *(const float4*)(B + (size_t)(kb + rr) * Nn + colBase + c2);
                *(float4*)(Bs + rr * 64 + c2) = v;
            }
        }
        __syncthreads();
#pragma unroll
        for (int kk = 0; kk < 32; kk++) {
            const ull* bp = (const ull*)(Bs + kk * 64 + tx * 4);
            ull b0 = bp[0], b1 = bp[1];
#pragma unroll
            for (int i = 0; i < 4; i++) {
                ull aa = pack2(As[(ty * 4 + i) * 32 + kk]);
                fma2(acc[i][0], aa, b0);
                fma2(acc[i][1], aa, b1);
            }
        }
        __syncthreads();
    }
#pragma unroll
    for (int i = 0; i < 4; i++) {
        int grow = rowBase + ty * 4 + i;
        if (grow < M) {
            float2 p0 = unpack2(acc[i][0]);
            float2 p1 = unpack2(acc[i][1]);
            *(float4*)(C + (size_t)grow * Nn + colBase + tx * 4) =
                make_float4(p0.x, p0.y, p1.x, p1.y);
        }
    }
}

// ---------------- el/er: per (node, head) dot over D ----------------
template <int D>
__global__ void k_elr(const float* __restrict__ lin,
                      const float* __restrict__ al,
                      const float* __restrict__ ar,
                      float* __restrict__ elo, float* __restrict__ ero) {
    int i = blockIdx.x * blockDim.x + threadIdx.x;
    if (i >= NN * NH) return;
    int n = i / NH, h = i % NH;
    float el = 0.f, er = 0.f;
#pragma unroll
    for (int d = 0; d < D; d++) {
        float v = lin[n * (NH * D) + h * D + d];
        el += v * al[h * D + d];
        er += v * ar[h * D + d];
    }
    elo[i] = el;
    ero[i] = er;
}

// ---------------- fused per-node GAT: e, max, exp, sum, aggregate ----------------
template <int D, bool RELU>
__global__ void k_gat_fused(const float* __restrict__ lin,
                            const float* __restrict__ elp,
                            const float* __restrict__ erp,
                            const float* __restrict__ bias,
                            float* __restrict__ out) {
    const int C = NH * D;
    int n = blockIdx.x;
    int tid = threadIdx.x;     // 0..C-1
    int beg = g_off[n], end = g_off[n + 1];
    __shared__ int   s_m[NH];       // float-as-int max
    __shared__ float s_sum[NH];
    __shared__ int   s_src[32];
    __shared__ float s_ex[32 * NH];
    if (tid < NH) { s_m[tid] = __float_as_int(-INFINITY); s_sum[tid] = 0.f; }
    __syncthreads();

    // pass 1: compute e (leaky relu), block max per head
    {
        int h = tid & 7;
        float ern = erp[n * NH + h];
        for (int j0 = beg + (tid >> 3); j0 < end; j0 += C / NH) {
            int s = g_ssrc[j0];
            float v = elp[s * NH + h] + ern;
            v = (v > 0.f) ? v : NEG_SLOPE * v;
            g_e[(size_t)j0 * NH + h] = v;
            if (v >= 0.f)
                atomicMax(&s_m[h], __float_as_int(v));
            else
                atomicMin((unsigned int*)&s_m[h], (unsigned int)__float_as_int(v));
        }
    }
    __syncthreads();
    float mh[1];
    // pass 2+3: exp + sum + aggregate in 32-edge chunks
    float acc = 0.f;
    int hA = tid / D;
    for (int base = beg; base < end; base += 32) {
        int cnt = min(32, end - base);
        __syncthreads();
        if (tid < cnt) s_src[tid] = g_ssrc[base + tid];
        for (int i = tid; i < cnt * NH; i += C) {
            float ex = __expf(g_e[(size_t)base * NH + i] - __int_as_float(s_m[i & 7]));
            s_ex[i] = ex;
            atomicAdd(&s_sum[i & 7], ex);
        }
        __syncthreads();
        for (int jj = 0; jj < cnt; jj++)
            acc += lin[(size_t)s_src[jj] * C + tid] * s_ex[jj * NH + hA];
    }
    float v = (end > beg) ? acc / s_sum[hA] : 0.f;
    v += bias[tid];
    if (RELU) v = fmaxf(v, 0.f);
    out[(size_t)n * C + tid] = v;
    (void)mh;
}

// ---------------- z = mean + noise * exp(log_std) ----------------
__global__ void k_z(const float* __restrict__ noise, float* __restrict__ zout) {
    int i = blockIdx.x * blockDim.x + threadIdx.x;
    if (i < NN * ZC) zout[i] = g_mean[i] + noise[i] * expf(g_lstd[i]);
}

// ---------------- adj = sigmoid(z @ z^T), f32x2 FMAs ----------------
#define ADJ_LDT 132
#define ADJ_SMEM (2 * 64 * ADJ_LDT * 4)
__global__ __launch_bounds__(256) void k_adj(const float* __restrict__ z,
                                             float* __restrict__ adj) {
    extern __shared__ float sm[];
    float* Azt = sm;                   // [k][row_local]
    float* Bzt = sm + 64 * ADJ_LDT;    // [k][col_local]
    int tid = threadIdx.x;
    int tx = tid & 15, ty = tid >> 4;
    int row0 = blockIdx.y * 128;
    int col0 = blockIdx.x * 128;

#pragma unroll
    for (int p = 0; p < 8; p++) {
        int nl = p * 16 + (tid >> 4);
        int k4 = (tid & 15) << 2;
        int ra = row0 + nl;
        float4 va = (ra < NN) ? *(const float4*)(z + (size_t)ra * ZC + k4)
                              : make_float4(0.f, 0.f, 0.f, 0.f);
        Azt[(k4 + 0) * ADJ_LDT + nl] = va.x;
        Azt[(k4 + 1) * ADJ_LDT + nl] = va.y;
        Azt[(k4 + 2) * ADJ_LDT + nl] = va.z;
        Azt[(k4 + 3) * ADJ_LDT + nl] = va.w;
        int rb = col0 + nl;
        float4 vb = (rb < NN) ? *(const float4*)(z + (size_t)rb * ZC + k4)
                              : make_float4(0.f, 0.f, 0.f, 0.f);
        Bzt[(k4 + 0) * ADJ_LDT + nl] = vb.x;
        Bzt[(k4 + 1) * ADJ_LDT + nl] = vb.y;
        Bzt[(k4 + 2) * ADJ_LDT + nl] = vb.z;
        Bzt[(k4 + 3) * ADJ_LDT + nl] = vb.w;
    }
    __syncthreads();

    ull acc[8][4] = {};
#pragma unroll
    for (int k = 0; k < 64; k++) {
        const float* ap = Azt + k * ADJ_LDT + ty * 8;
        float4 a0 = *(const float4*)ap;
        float4 a1 = *(const float4*)(ap + 4);
        const ull* bp = (const ull*)(Bzt + k * ADJ_LDT + tx * 8);
        ull b0 = bp[0], b1 = bp[1], b2 = bp[2], b3 = bp[3];
        float a[8] = {a0.x, a0.y, a0.z, a0.w, a1.x, a1.y, a1.z, a1.w};
#pragma unroll
        for (int i = 0; i < 8; i++) {
            ull aa = pack2(a[i]);
            fma2(acc[i][0], aa, b0);
            fma2(acc[i][1], aa, b1);
            fma2(acc[i][2], aa, b2);
            fma2(acc[i][3], aa, b3);
        }
    }

#pragma unroll
    for (int i = 0; i < 8; i++) {
        int r = row0 + ty * 8 + i;
        if (r >= NN) continue;
        float* outrow = adj + (size_t)r * NN;
        int c = col0 + tx * 8;
        float vals[8];
#pragma unroll
        for (int p = 0; p < 4; p++) {
            float2 u = unpack2(acc[i][p]);
            vals[2 * p] = u.x;
            vals[2 * p + 1] = u.y;
        }
#pragma unroll
        for (int jj = 0; jj < 8; jj++) vals[jj] = 1.f / (1.f + __expf(-vals[jj]));
        if (c + 7 < NN) {
            *(float4*)(outrow + c) = make_float4(vals[0], vals[1], vals[2], vals[3]);
            *(float4*)(outrow + c + 4) = make_float4(vals[4], vals[5], vals[6], vals[7]);
        } else {
#pragma unroll
            for (int jj = 0; jj < 8; jj++)
                if (c + jj < NN) outrow[c + jj] = vals[jj];
        }
    }
}

// ---------------- launcher ----------------
extern "C" void kernel_launch(void* const* d_in, const int* in_sizes, int n_in,
                              void* d_out, int out_size) {
    const float* features = (const float*)d_in[0];
    const int*   src      = (const int*)d_in[1];
    const int*   dst      = (const int*)d_in[2];
    const float* noise    = (const float*)d_in[3];
    const float* W0  = (const float*)d_in[4];
    const float* al0 = (const float*)d_in[5];
    const float* ar0 = (const float*)d_in[6];
    const float* b0  = (const float*)d_in[7];
    const float* W1  = (const float*)d_in[8];
    const float* al1 = (const float*)d_in[9];
    const float* ar1 = (const float*)d_in[10];
    const float* b1  = (const float*)d_in[11];
    const float* W2  = (const float*)d_in[12];
    const float* al2 = (const float*)d_in[13];
    const float* ar2 = (const float*)d_in[14];
    const float* b2  = (const float*)d_in[15];

    float* out = (float*)d_out;
    float* z_out = out;
    float* adj_out = out + (size_t)NN * ZC;

    void* p;
    cudaGetSymbolAddress(&p, g_lin0); float* lin0 = (float*)p;
    cudaGetSymbolAddress(&p, g_gat0); float* gat0 = (float*)p;
    cudaGetSymbolAddress(&p, g_lin1); float* lin1 = (float*)p;
    cudaGetSymbolAddress(&p, g_lin2); float* lin2 = (float*)p;
    cudaGetSymbolAddress(&p, g_mean); float* meanp = (float*)p;
    cudaGetSymbolAddress(&p, g_lstd); float* lstdp = (float*)p;
    cudaGetSymbolAddress(&p, g_el);  float* el = (float*)p;
    cudaGetSymbolAddress(&p, g_er);  float* er = (float*)p;
    cudaGetSymbolAddress(&p, g_el2); float* el2 = (float*)p;
    cudaGetSymbolAddress(&p, g_er2); float* er2 = (float*)p;

    // edge sort by dst (shared by all 3 GAT layers)
    k_zero_deg<<<(NN + 255) / 256, 256>>>();
    k_hist<<<(NE + 255) / 256, 256>>>(dst);
    k_scan<<<1, 1024>>>();
    k_scatter<<<(NE + 255) / 256, 256>>>(src, dst);

    const int ngrid = (NN * NH + 255) / 256;

    // ---- layer 0: 512 -> 256, relu ----
    k_sgemm<<<dim3(HIDC / 64, (NN + 63) / 64), 256>>>(features, W0, lin0, NN, FIN, HIDC);
    k_elr<ND0><<<ngrid, 256>>>(lin0, al0, ar0, el, er);
    k_gat_fused<ND0, true><<<NN, HIDC>>>(lin0, el, er, b0, gat0);

    // ---- layers 1 & 2: 256 -> 64 ----
    k_sgemm<<<dim3(ZC / 64, (NN + 63) / 64), 256>>>(gat0, W1, lin1, NN, HIDC, ZC);
    k_sgemm<<<dim3(ZC / 64, (NN + 63) / 64), 256>>>(gat0, W2, lin2, NN, HIDC, ZC);
    k_elr<ND1><<<ngrid, 256>>>(lin1, al1, ar1, el, er);
    k_elr<ND1><<<ngrid, 256>>>(lin2, al2, ar2, el2, er2);
    k_gat_fused<ND1, false><<<NN, ZC>>>(lin1, el, er, b1, meanp);
    k_gat_fused<ND1, false><<<NN, ZC>>>(lin2, el2, er2, b2, lstdp);

    // ---- z = mean + noise * exp(log_std) ----
    k_z<<<(NN * ZC + 255) / 256, 256>>>(noise, z_out);

    // ---- adj = sigmoid(z @ z^T) ----
    cudaFuncSetAttribute(k_adj, cudaFuncAttributeMaxDynamicSharedMemorySize, ADJ_SMEM);
    k_adj<<<dim3((NN + 127) / 128, (NN + 127) / 128), 256, ADJ_SMEM>>>(z_out, adj_out);
}

// round 4
// speedup vs baseline: 1.7813x; 1.7813x over previous
#include <cuda_runtime.h>
#include <cuda_bf16.h>
#include <cstdint>
#include <math.h>

#define NN 10000
#define NE 320000
#define FIN 512
#define HIDC 256
#define ZC 64
#define NH 8
#define ND0 32
#define ND1 8
#define NEG_SLOPE 0.2f

// ---------------- scratch (static device memory; no allocations) ----------------
__device__ float g_lin0[NN * HIDC];
__device__ float g_gat0[NN * HIDC];
__device__ float g_lin1[NN * ZC];
__device__ float g_lin2[NN * ZC];
__device__ float g_mean[NN * ZC];
__device__ float g_lstd[NN * ZC];
__device__ float g_el[NN * NH];
__device__ float g_er[NN * NH];
__device__ float g_m[NN * NH];
__device__ float g_s[NN * NH];
__device__ float g_e[NE * NH];
__device__ int   g_deg[NN];
__device__ int   g_off[NN + 1];
__device__ int   g_cur[NN];
__device__ int   g_ssrc[NE];
__device__ int   g_sdst[NE];
__device__ __nv_bfloat16 g_zhi[NN * ZC];
__device__ __nv_bfloat16 g_zlo[NN * ZC];

// ---------------- counting sort of edges by dst ----------------
__global__ void k_zero_deg() {
    int i = blockIdx.x * blockDim.x + threadIdx.x;
    if (i < NN) g_deg[i] = 0;
}

__global__ void k_hist(const int* __restrict__ dst) {
    int i = blockIdx.x * blockDim.x + threadIdx.x;
    if (i < NE) atomicAdd(&g_deg[dst[i]], 1);
}

__global__ void k_scan() {
    const int CH = 10;
    __shared__ int sh[1024];
    int t = threadIdx.x;
    int base = t * CH;
    int vals[CH];
    int loc = 0;
#pragma unroll
    for (int i = 0; i < CH; i++) {
        int idx = base + i;
        vals[i] = (idx < NN) ? g_deg[idx] : 0;
        loc += vals[i];
    }
    sh[t] = loc;
    __syncthreads();
    for (int off = 1; off < 1024; off <<= 1) {
        int v = (t >= off) ? sh[t - off] : 0;
        __syncthreads();
        sh[t] += v;
        __syncthreads();
    }
    int run = sh[t] - loc;
#pragma unroll
    for (int i = 0; i < CH; i++) {
        int idx = base + i;
        if (idx < NN) {
            g_off[idx] = run;
            g_cur[idx] = run;
            run += vals[i];
        }
    }
    if (t == 0) g_off[NN] = NE;
}

__global__ void k_scatter(const int* __restrict__ src, const int* __restrict__ dst) {
    int e = blockIdx.x * blockDim.x + threadIdx.x;
    if (e < NE) {
        int d = dst[e];
        int pos = atomicAdd(&g_cur[d], 1);
        g_ssrc[pos] = src[e];
        g_sdst[pos] = d;
    }
}

// ---------------- fp32 tiled GEMM (round-1 plain FFMA version) ----------------
__global__ __launch_bounds__(256) void k_sgemm(const float* __restrict__ A,
                                               const float* __restrict__ B,
                                               float* __restrict__ C,
                                               int M, int K, int Nn) {
    __shared__ float As[64 * 32];
    __shared__ float Bs[32 * 64];
    int tid = threadIdx.x;
    int tx = tid & 15, ty = tid >> 4;
    int rowBase = blockIdx.y * 64;
    int colBase = blockIdx.x * 64;
    float acc[4][4] = {};

    for (int kb = 0; kb < K; kb += 32) {
        {
            int r = tid >> 3;
            int c = (tid & 7) << 2;
#pragma unroll
            for (int p = 0; p < 2; p++) {
                int rr = r + p * 32;
                int grow = rowBase + rr;
                float4 v = make_float4(0.f, 0.f, 0.f, 0.f);
                if (grow < M) v = *(const float4*)(A + (size_t)grow * K + kb + c);
                *(float4*)(As + rr * 32 + c) = v;
            }
            int r2 = tid >> 4;
            int c2 = (tid & 15) << 2;
#pragma unroll
            for (int p = 0; p < 2; p++) {
                int rr = r2 + p * 16;
                float4 v = *(const float4*)(B + (size_t)(kb + rr) * Nn + colBase + c2);
                *(float4*)(Bs + rr * 64 + c2) = v;
            }
        }
        __syncthreads();
#pragma unroll
        for (int kk = 0; kk < 32; kk++) {
            float4 b0 = *(const float4*)(Bs + kk * 64 + tx * 4);
            float a0 = As[(ty * 4 + 0) * 32 + kk];
            float a1 = As[(ty * 4 + 1) * 32 + kk];
            float a2 = As[(ty * 4 + 2) * 32 + kk];
            float a3 = As[(ty * 4 + 3) * 32 + kk];
            acc[0][0] += a0 * b0.x; acc[0][1] += a0 * b0.y; acc[0][2] += a0 * b0.z; acc[0][3] += a0 * b0.w;
            acc[1][0] += a1 * b0.x; acc[1][1] += a1 * b0.y; acc[1][2] += a1 * b0.z; acc[1][3] += a1 * b0.w;
            acc[2][0] += a2 * b0.x; acc[2][1] += a2 * b0.y; acc[2][2] += a2 * b0.z; acc[2][3] += a2 * b0.w;
            acc[3][0] += a3 * b0.x; acc[3][1] += a3 * b0.y; acc[3][2] += a3 * b0.z; acc[3][3] += a3 * b0.w;
        }
        __syncthreads();
    }
#pragma unroll
    for (int i = 0; i < 4; i++) {
        int grow = rowBase + ty * 4 + i;
        if (grow < M) {
            *(float4*)(C + (size_t)grow * Nn + colBase + tx * 4) =
                make_float4(acc[i][0], acc[i][1], acc[i][2], acc[i][3]);
        }
    }
}

// ---------------- el/er ----------------
template <int D>
__global__ void k_elr(const float* __restrict__ lin,
                      const float* __restrict__ al,
                      const float* __restrict__ ar) {
    int i = blockIdx.x * blockDim.x + threadIdx.x;
    if (i >= NN * NH) return;
    int n = i / NH, h = i % NH;
    float el = 0.f, er = 0.f;
#pragma unroll
    for (int d = 0; d < D; d++) {
        float v = lin[n * (NH * D) + h * D + d];
        el += v * al[h * D + d];
        er += v * ar[h * D + d];
    }
    g_el[i] = el;
    g_er[i] = er;
}

__global__ void k_init_ms() {
    int i = blockIdx.x * blockDim.x + threadIdx.x;
    if (i < NN * NH) {
        g_m[i] = -INFINITY;
        g_s[i] = 0.f;
    }
}

__device__ __forceinline__ void atomicMaxFloat(float* addr, float val) {
    if (val >= 0.f)
        atomicMax((int*)addr, __float_as_int(val));
    else
        atomicMin((unsigned int*)addr, (unsigned int)__float_as_int(val));
}

__global__ void k_edge1() {
    int idx = blockIdx.x * blockDim.x + threadIdx.x;
    if (idx >= NE * NH) return;
    int j = idx >> 3;
    int h = idx & 7;
    int s = g_ssrc[j];
    int d = g_sdst[j];
    float v = g_el[s * NH + h] + g_er[d * NH + h];
    v = (v > 0.f) ? v : NEG_SLOPE * v;
    g_e[idx] = v;
    atomicMaxFloat(&g_m[d * NH + h], v);
}

__global__ void k_edge2() {
    int idx = blockIdx.x * blockDim.x + threadIdx.x;
    if (idx >= NE * NH) return;
    int j = idx >> 3;
    int h = idx & 7;
    int d = g_sdst[j];
    float ex = expf(g_e[idx] - g_m[d * NH + h]);
    g_e[idx] = ex;
    atomicAdd(&g_s[d * NH + h], ex);
}

// ---------------- CSR aggregation ----------------
template <int D, bool RELU>
__global__ void k_agg(const float* __restrict__ lin,
                      const float* __restrict__ bias,
                      float* __restrict__ out) {
    const int C = NH * D;
    int n = blockIdx.x;
    int tid = threadIdx.x;
    int h = tid / D;
    int beg = g_off[n], end = g_off[n + 1];
    float acc = 0.f;
    __shared__ int s_src[32];
    __shared__ float s_ex[32 * NH];
    for (int base = beg; base < end; base += 32) {
        int cnt = min(32, end - base);
        __syncthreads();
        if (tid < cnt) s_src[tid] = g_ssrc[base + tid];
        for (int i = tid; i < cnt * NH; i += C) s_ex[i] = g_e[base * NH + i];
        __syncthreads();
        for (int jj = 0; jj < cnt; jj++) {
            acc += lin[(size_t)s_src[jj] * C + tid] * s_ex[jj * NH + h];
        }
    }
    float v = (end > beg) ? (acc / g_s[n * NH + h]) : 0.f;
    v += bias[tid];
    if (RELU) v = fmaxf(v, 0.f);
    out[(size_t)n * C + tid] = v;
}

// ---------------- z = mean + noise * exp(log_std), then bf16 hi/lo split ----------------
__global__ void k_z(const float* __restrict__ noise, float* __restrict__ zout) {
    int i = blockIdx.x * blockDim.x + threadIdx.x;
    if (i < NN * ZC) zout[i] = g_mean[i] + noise[i] * expf(g_lstd[i]);
}

__global__ void k_split(const float* __restrict__ z) {
    int i = blockIdx.x * blockDim.x + threadIdx.x;
    if (i >= NN * ZC) return;
    float v = z[i];
    __nv_bfloat16 h = __float2bfloat16(v);
    g_zhi[i] = h;
    g_zlo[i] = __float2bfloat16(v - __bfloat162float(h));
}

// ---------------- adj = sigmoid(z @ z^T) via bf16 mma, hi/lo split ----------------
// block: 128x128 tile, 8 warps (2x4), warp tile 64x32, mma m16n8k16
#define ALD 72                // bf16 leading dim (64 + 8 pad) -> conflict-free b32 LDS
#define ALD32 36
#define ADJ_MMA_SMEM (4 * 128 * ALD * 2)

__global__ __launch_bounds__(256) void k_adj_mma(float* __restrict__ adj) {
    extern __shared__ __nv_bfloat16 smb[];
    __nv_bfloat16* Ah = smb;
    __nv_bfloat16* Al = Ah + 128 * ALD;
    __nv_bfloat16* Bh = Al + 128 * ALD;
    __nv_bfloat16* Bl = Bh + 128 * ALD;
    int tid = threadIdx.x;
    int row0 = blockIdx.y * 128;
    int col0 = blockIdx.x * 128;

    // load A (rows) and B (cols) tiles of z_hi / z_lo
    for (int idx = tid; idx < 128 * 8; idx += 256) {
        int r = idx >> 3;
        int c8 = (idx & 7) * 8;     // bf16 column, 8 per uint4
        uint4 zero4 = make_uint4(0, 0, 0, 0);
        int ra = row0 + r;
        uint4 vah = zero4, val = zero4;
        if (ra < NN) {
            vah = *(const uint4*)(g_zhi + (size_t)ra * ZC + c8);
            val = *(const uint4*)(g_zlo + (size_t)ra * ZC + c8);
        }
        *(uint4*)(Ah + r * ALD + c8) = vah;
        *(uint4*)(Al + r * ALD + c8) = val;
        int rb = col0 + r;
        uint4 vbh = zero4, vbl = zero4;
        if (rb < NN) {
            vbh = *(const uint4*)(g_zhi + (size_t)rb * ZC + c8);
            vbl = *(const uint4*)(g_zlo + (size_t)rb * ZC + c8);
        }
        *(uint4*)(Bh + r * ALD + c8) = vbh;
        *(uint4*)(Bl + r * ALD + c8) = vbl;
    }
    __syncthreads();

    int warp = tid >> 5, lane = tid & 31;
    int wm = warp >> 2, wn = warp & 3;   // 2 x 4 warp grid
    int lr = lane >> 2, lq = lane & 3;

    float acc[16][4];
#pragma unroll
    for (int i = 0; i < 16; i++)
#pragma unroll
        for (int j = 0; j < 4; j++) acc[i][j] = 0.f;

    // passes: hi*hi, hi*lo, lo*hi  (drop lo*lo)
    const uint32_t* Aptr[3] = {(const uint32_t*)Ah, (const uint32_t*)Ah, (const uint32_t*)Al};
    const uint32_t* Bptr[3] = {(const uint32_t*)Bh, (const uint32_t*)Bl, (const uint32_t*)Bh};

#pragma unroll
    for (int p = 0; p < 3; p++) {
        const uint32_t* As = Aptr[p];
        const uint32_t* Bs = Bptr[p];
#pragma unroll
        for (int ks = 0; ks < 4; ks++) {      // K = 64 = 4 x 16
            uint32_t af[4][4], bfr[4][2];
#pragma unroll
            for (int mt = 0; mt < 4; mt++) {
                int rowA = wm * 64 + mt * 16 + lr;
                const uint32_t* pa = As + rowA * ALD32 + ks * 8 + lq;
                af[mt][0] = pa[0];
                af[mt][1] = pa[8 * ALD32];
                af[mt][2] = pa[4];
                af[mt][3] = pa[8 * ALD32 + 4];
            }
#pragma unroll
            for (int nt = 0; nt < 4; nt++) {
                int colB = wn * 32 + nt * 8 + lr;
                const uint32_t* pb = Bs + colB * ALD32 + ks * 8 + lq;
                bfr[nt][0] = pb[0];
                bfr[nt][1] = pb[4];
            }
#pragma unroll
            for (int mt = 0; mt < 4; mt++)
#pragma unroll
                for (int nt = 0; nt < 4; nt++) {
                    float* d = acc[mt * 4 + nt];
                    asm volatile(
                        "mma.sync.aligned.m16n8k16.row.col.f32.bf16.bf16.f32 "
                        "{%0,%1,%2,%3}, {%4,%5,%6,%7}, {%8,%9}, {%0,%1,%2,%3};"
                        : "+f"(d[0]), "+f"(d[1]), "+f"(d[2]), "+f"(d[3])
                        : "r"(af[mt][0]), "r"(af[mt][1]), "r"(af[mt][2]), "r"(af[mt][3]),
                          "r"(bfr[nt][0]), "r"(bfr[nt][1]));
                }
        }
    }

    // epilogue: sigmoid + store
#pragma unroll
    for (int mt = 0; mt < 4; mt++) {
        int r = row0 + wm * 64 + mt * 16 + lr;
#pragma unroll
        for (int nt = 0; nt < 4; nt++) {
            int c = col0 + wn * 32 + nt * 8 + lq * 2;
            float* d = acc[mt * 4 + nt];
            float s0 = 1.f / (1.f + __expf(-d[0]));
            float s1 = 1.f / (1.f + __expf(-d[1]));
            float s2 = 1.f / (1.f + __expf(-d[2]));
            float s3 = 1.f / (1.f + __expf(-d[3]));
            if (c < NN) {
                if (r < NN)
                    *(float2*)(adj + (size_t)r * NN + c) = make_float2(s0, s1);
                if (r + 8 < NN)
                    *(float2*)(adj + (size_t)(r + 8) * NN + c) = make_float2(s2, s3);
            }
        }
    }
}

// ---------------- launcher ----------------
extern "C" void kernel_launch(void* const* d_in, const int* in_sizes, int n_in,
                              void* d_out, int out_size) {
    const float* features = (const float*)d_in[0];
    const int*   src      = (const int*)d_in[1];
    const int*   dst      = (const int*)d_in[2];
    const float* noise    = (const float*)d_in[3];
    const float* W0  = (const float*)d_in[4];
    const float* al0 = (const float*)d_in[5];
    const float* ar0 = (const float*)d_in[6];
    const float* b0  = (const float*)d_in[7];
    const float* W1  = (const float*)d_in[8];
    const float* al1 = (const float*)d_in[9];
    const float* ar1 = (const float*)d_in[10];
    const float* b1  = (const float*)d_in[11];
    const float* W2  = (const float*)d_in[12];
    const float* al2 = (const float*)d_in[13];
    const float* ar2 = (const float*)d_in[14];
    const float* b2  = (const float*)d_in[15];

    float* out = (float*)d_out;
    float* z_out = out;
    float* adj_out = out + (size_t)NN * ZC;

    void* p;
    cudaGetSymbolAddress(&p, g_lin0); float* lin0 = (float*)p;
    cudaGetSymbolAddress(&p, g_gat0); float* gat0 = (float*)p;
    cudaGetSymbolAddress(&p, g_lin1); float* lin1 = (float*)p;
    cudaGetSymbolAddress(&p, g_lin2); float* lin2 = (float*)p;
    cudaGetSymbolAddress(&p, g_mean); float* meanp = (float*)p;
    cudaGetSymbolAddress(&p, g_lstd); float* lstdp = (float*)p;

    // edge sort by dst (shared by all 3 GAT layers)
    k_zero_deg<<<(NN + 255) / 256, 256>>>();
    k_hist<<<(NE + 255) / 256, 256>>>(dst);
    k_scan<<<1, 1024>>>();
    k_scatter<<<(NE + 255) / 256, 256>>>(src, dst);

    const int egrid = (NE * NH + 255) / 256;
    const int ngrid = (NN * NH + 255) / 256;

    // ---- layer 0: 512 -> 256, relu ----
    k_sgemm<<<dim3(HIDC / 64, (NN + 63) / 64), 256>>>(features, W0, lin0, NN, FIN, HIDC);
    k_elr<ND0><<<ngrid, 256>>>(lin0, al0, ar0);
    k_init_ms<<<ngrid, 256>>>();
    k_edge1<<<egrid, 256>>>();
    k_edge2<<<egrid, 256>>>();
    k_agg<ND0, true><<<NN, NH * ND0>>>(lin0, b0, gat0);

    // ---- layer 1 (mean): 256 -> 64 ----
    k_sgemm<<<dim3(ZC / 64, (NN + 63) / 64), 256>>>(gat0, W1, lin1, NN, HIDC, ZC);
    k_elr<ND1><<<ngrid, 256>>>(lin1, al1, ar1);
    k_init_ms<<<ngrid, 256>>>();
    k_edge1<<<egrid, 256>>>();
    k_edge2<<<egrid, 256>>>();
    k_agg<ND1, false><<<NN, NH * ND1>>>(lin1, b1, meanp);

    // ---- layer 2 (log_std): 256 -> 64 ----
    k_sgemm<<<dim3(ZC / 64, (NN + 63) / 64), 256>>>(gat0, W2, lin2, NN, HIDC, ZC);
    k_elr<ND1><<<ngrid, 256>>>(lin2, al2, ar2);
    k_init_ms<<<ngrid, 256>>>();
    k_edge1<<<egrid, 256>>>();
    k_edge2<<<egrid, 256>>>();
    k_agg<ND1, false><<<NN, NH * ND1>>>(lin2, b2, lstdp);

    // ---- z = mean + noise * exp(log_std), split to bf16 hi/lo ----
    k_z<<<(NN * ZC + 255) / 256, 256>>>(noise, z_out);
    k_split<<<(NN * ZC + 255) / 256, 256>>>(z_out);

    // ---- adj = sigmoid(z @ z^T) via tensor cores ----
    cudaFuncSetAttribute(k_adj_mma, cudaFuncAttributeMaxDynamicSharedMemorySize, ADJ_MMA_SMEM);
    k_adj_mma<<<dim3((NN + 127) / 128, (NN + 127) / 128), 256, ADJ_MMA_SMEM>>>(adj_out);
}

// round 6
// speedup vs baseline: 2.1343x; 1.1982x over previous
#include <cuda_runtime.h>
#include <cuda_bf16.h>
#include <cstdint>
#include <math.h>

#define NN 10000
#define NPAD 10112           // 79 * 128
#define NE 320000
#define FIN 512
#define HIDC 256
#define ZC 64
#define NH 8
#define ND0 32
#define ND1 8
#define NEG_SLOPE 0.2f

// ---------------- scratch (static device memory; no allocations) ----------------
__device__ float g_lin0[NN * HIDC];
__device__ float g_gat0[NN * HIDC];
__device__ float g_lin1[NN * ZC];
__device__ float g_lin2[NN * ZC];
__device__ float g_mean[NN * ZC];
__device__ float g_lstd[NN * ZC];
__device__ float g_el[NN * NH];
__device__ float g_er[NN * NH];
__device__ float g_m[NN * NH];
__device__ float g_s[NN * NH];
__device__ float g_e[NE * NH];
__device__ int   g_deg[NN];
__device__ int   g_off[NN + 1];
__device__ int   g_cur[NN];
__device__ int   g_ssrc[NE];
__device__ int   g_sdst[NE];
__device__ __nv_bfloat16 g_zhi[NPAD * ZC];
__device__ __nv_bfloat16 g_zlo[NPAD * ZC];

// Feature gate: tcgen05 only exists on the 'a' targets. The harness also runs a
// plain compute_103 PTX pass; compile an empty body there (runtime picks sm_103a cubin).
#if defined(__CUDA_ARCH_FEAT_SM103_ALL) || defined(__CUDA_ARCH_FEAT_SM100_ALL) || defined(__CUDA_ARCH_FEAT_SM101_ALL)
#define HAS_TCGEN05 1
#else
#define HAS_TCGEN05 0
#endif

// ---------------- PTX helpers ----------------
__device__ __forceinline__ uint32_t smem_u32(const void* p) {
    uint32_t a;
    asm("{ .reg .u64 t; cvta.to.shared.u64 t, %1; cvt.u32.u64 %0, t; }" : "=r"(a) : "l"(p));
    return a;
}
__device__ __forceinline__ uint32_t elect1() {
    uint32_t r;
    asm volatile("{ .reg .pred p; elect.sync _|p, 0xFFFFFFFF; selp.b32 %0,1,0,p; }" : "=r"(r));
    return r;
}
#define MBAR_INIT(mbar, cnt) \
    asm volatile("mbarrier.init.shared.b64 [%0], %1;" :: "r"((uint32_t)(mbar)), "r"((uint32_t)(cnt)) : "memory")
#define MBAR_INVAL(mbar) \
    asm volatile("mbarrier.inval.shared.b64 [%0];" :: "r"((uint32_t)(mbar)) : "memory")
#define MBAR_WAIT(mbar, parity) do {                                           \
    uint32_t _m = (uint32_t)(mbar), _p = (uint32_t)(parity), _d;               \
    asm volatile("{ .reg .pred p; mbarrier.try_wait.parity.acquire.cta.shared::cta.b64 p, [%1], %2; selp.b32 %0,1,0,p; }" \
                 : "=r"(_d) : "r"(_m), "r"(_p) : "memory");                    \
    if (!_d) {                                                                 \
        asm volatile("{ .reg .pred P1; WL%=: mbarrier.try_wait.parity.acquire.cta.shared::cta.b64 P1, [%0], %1, 0x989680; @P1 bra.uni WD%=; bra.uni WL%=; WD%=: }" \
                     :: "r"(_m), "r"(_p) : "memory");                          \
    }                                                                          \
} while (0)

#if HAS_TCGEN05
#define TC_ALLOC(saddr, n) \
    asm volatile("tcgen05.alloc.cta_group::1.sync.aligned.shared::cta.b32 [%0], %1;" \
                 :: "r"((uint32_t)(saddr)), "r"((uint32_t)(n)) : "memory")
#define TC_RELINQ() \
    asm volatile("tcgen05.relinquish_alloc_permit.cta_group::1.sync.aligned;")
#define TC_DEALLOC(tmem, n) \
    asm volatile("tcgen05.dealloc.cta_group::1.sync.aligned.b32 %0, %1;" :: "r"(tmem), "r"((uint32_t)(n)))
#define TC_COMMIT(mbar) \
    asm volatile("tcgen05.commit.cta_group::1.mbarrier::arrive::one.shared::cluster.b64 [%0];" \
                 :: "r"((uint32_t)(mbar)) : "memory")
#define TC_FENCE_AFTER() asm volatile("tcgen05.fence::after_thread_sync;" ::: "memory")
#define TC_FENCE_BEFORE() asm volatile("tcgen05.fence::before_thread_sync;" ::: "memory")
#define TC_WAIT_LD() asm volatile("tcgen05.wait::ld.sync.aligned;" ::: "memory")
#define TC_LD_X32(r, tmem_addr) \
    asm volatile( \
        "tcgen05.ld.sync.aligned.32x32b.x32.b32 " \
        "{%0, %1, %2, %3, %4, %5, %6, %7, " \
        " %8, %9, %10, %11, %12, %13, %14, %15, " \
        " %16, %17, %18, %19, %20, %21, %22, %23, " \
        " %24, %25, %26, %27, %28, %29, %30, %31}, [%32];" \
        : "=r"((r)[0]),  "=r"((r)[1]),  "=r"((r)[2]),  "=r"((r)[3]), \
          "=r"((r)[4]),  "=r"((r)[5]),  "=r"((r)[6]),  "=r"((r)[7]), \
          "=r"((r)[8]),  "=r"((r)[9]),  "=r"((r)[10]), "=r"((r)[11]), \
          "=r"((r)[12]), "=r"((r)[13]), "=r"((r)[14]), "=r"((r)[15]), \
          "=r"((r)[16]), "=r"((r)[17]), "=r"((r)[18]), "=r"((r)[19]), \
          "=r"((r)[20]), "=r"((r)[21]), "=r"((r)[22]), "=r"((r)[23]), \
          "=r"((r)[24]), "=r"((r)[25]), "=r"((r)[26]), "=r"((r)[27]), \
          "=r"((r)[28]), "=r"((r)[29]), "=r"((r)[30]), "=r"((r)[31]) \
        : "r"(tmem_addr))

__device__ __forceinline__ void mma_f16_ss(uint32_t d, uint64_t a, uint64_t b,
                                           uint32_t idesc, bool accum) {
    uint32_t en = accum ? 1u : 0u;
    asm volatile(
        "{\n\t"
        ".reg .pred p;\n\t"
        "setp.ne.u32 p, %5, 0;\n\t"
        "tcgen05.mma.cta_group::1.kind::f16 [%0], %1, %2, %3, {%4, %4, %4, %4}, p;\n\t"
        "}"
        :: "r"(d), "l"(a), "l"(b), "r"(idesc), "r"(0u), "r"(en)
        : "memory");
}
#endif  // HAS_TCGEN05

// SW128 SMEM descriptor (version=1, SBO=64, LBO=1), matches verified examples
__device__ __forceinline__ uint64_t mk_desc(uint32_t saddr) {
    const uint64_t BASE =
        (uint64_t(2) << 61) | (uint64_t(1) << 46) | (uint64_t(64) << 32) | (uint64_t(1) << 16);
    return BASE | ((uint64_t)(saddr >> 4) & 0x3FFF);
}
__device__ __forceinline__ uint32_t swz128(uint32_t off) {
    return off ^ ((off >> 3) & 0x70);
}

// ---------------- counting sort of edges by dst ----------------
__global__ void k_zero_deg() {
    int i = blockIdx.x * blockDim.x + threadIdx.x;
    if (i < NN) g_deg[i] = 0;
}

__global__ void k_hist(const int* __restrict__ dst) {
    int i = blockIdx.x * blockDim.x + threadIdx.x;
    if (i < NE) atomicAdd(&g_deg[dst[i]], 1);
}

__global__ void k_scan() {
    const int CH = 10;
    __shared__ int sh[1024];
    int t = threadIdx.x;
    int base = t * CH;
    int vals[CH];
    int loc = 0;
#pragma unroll
    for (int i = 0; i < CH; i++) {
        int idx = base + i;
        vals[i] = (idx < NN) ? g_deg[idx] : 0;
        loc += vals[i];
    }
    sh[t] = loc;
    __syncthreads();
    for (int off = 1; off < 1024; off <<= 1) {
        int v = (t >= off) ? sh[t - off] : 0;
        __syncthreads();
        sh[t] += v;
        __syncthreads();
    }
    int run = sh[t] - loc;
#pragma unroll
    for (int i = 0; i < CH; i++) {
        int idx = base + i;
        if (idx < NN) {
            g_off[idx] = run;
            g_cur[idx] = run;
            run += vals[i];
        }
    }
    if (t == 0) g_off[NN] = NE;
}

__global__ void k_scatter(const int* __restrict__ src, const int* __restrict__ dst) {
    int e = blockIdx.x * blockDim.x + threadIdx.x;
    if (e < NE) {
        int d = dst[e];
        int pos = atomicAdd(&g_cur[d], 1);
        g_ssrc[pos] = src[e];
        g_sdst[pos] = d;
    }
}

// ---------------- fp32 tiled GEMM ----------------
__global__ __launch_bounds__(256) void k_sgemm(const float* __restrict__ A,
                                               const float* __restrict__ B,
                                               float* __restrict__ C,
                                               int M, int K, int Nn) {
    __shared__ float As[64 * 32];
    __shared__ float Bs[32 * 64];
    int tid = threadIdx.x;
    int tx = tid & 15, ty = tid >> 4;
    int rowBase = blockIdx.y * 64;
    int colBase = blockIdx.x * 64;
    float acc[4][4] = {};

    for (int kb = 0; kb < K; kb += 32) {
        {
            int r = tid >> 3;
            int c = (tid & 7) << 2;
#pragma unroll
            for (int p = 0; p < 2; p++) {
                int rr = r + p * 32;
                int grow = rowBase + rr;
                float4 v = make_float4(0.f, 0.f, 0.f, 0.f);
                if (grow < M) v = *(const float4*)(A + (size_t)grow * K + kb + c);
                *(float4*)(As + rr * 32 + c) = v;
            }
            int r2 = tid >> 4;
            int c2 = (tid & 15) << 2;
#pragma unroll
            for (int p = 0; p < 2; p++) {
                int rr = r2 + p * 16;
                float4 v = *(const float4*)(B + (size_t)(kb + rr) * Nn + colBase + c2);
                *(float4*)(Bs + rr * 64 + c2) = v;
            }
        }
        __syncthreads();
#pragma unroll
        for (int kk = 0; kk < 32; kk++) {
            float4 b0 = *(const float4*)(Bs + kk * 64 + tx * 4);
            float a0 = As[(ty * 4 + 0) * 32 + kk];
            float a1 = As[(ty * 4 + 1) * 32 + kk];
            float a2 = As[(ty * 4 + 2) * 32 + kk];
            float a3 = As[(ty * 4 + 3) * 32 + kk];
            acc[0][0] += a0 * b0.x; acc[0][1] += a0 * b0.y; acc[0][2] += a0 * b0.z; acc[0][3] += a0 * b0.w;
            acc[1][0] += a1 * b0.x; acc[1][1] += a1 * b0.y; acc[1][2] += a1 * b0.z; acc[1][3] += a1 * b0.w;
            acc[2][0] += a2 * b0.x; acc[2][1] += a2 * b0.y; acc[2][2] += a2 * b0.z; acc[2][3] += a2 * b0.w;
            acc[3][0] += a3 * b0.x; acc[3][1] += a3 * b0.y; acc[3][2] += a3 * b0.z; acc[3][3] += a3 * b0.w;
        }
        __syncthreads();
    }
#pragma unroll
    for (int i = 0; i < 4; i++) {
        int grow = rowBase + ty * 4 + i;
        if (grow < M) {
            *(float4*)(C + (size_t)grow * Nn + colBase + tx * 4) =
                make_float4(acc[i][0], acc[i][1], acc[i][2], acc[i][3]);
        }
    }
}

// ---------------- el/er ----------------
template <int D>
__global__ void k_elr(const float* __restrict__ lin,
                      const float* __restrict__ al,
                      const float* __restrict__ ar) {
    int i = blockIdx.x * blockDim.x + threadIdx.x;
    if (i >= NN * NH) return;
    int n = i / NH, h = i % NH;
    float el = 0.f, er = 0.f;
#pragma unroll
    for (int d = 0; d < D; d++) {
        float v = lin[n * (NH * D) + h * D + d];
        el += v * al[h * D + d];
        er += v * ar[h * D + d];
    }
    g_el[i] = el;
    g_er[i] = er;
}

__global__ void k_init_ms() {
    int i = blockIdx.x * blockDim.x + threadIdx.x;
    if (i < NN * NH) {
        g_m[i] = -INFINITY;
        g_s[i] = 0.f;
    }
}

__device__ __forceinline__ void atomicMaxFloat(float* addr, float val) {
    if (val >= 0.f)
        atomicMax((int*)addr, __float_as_int(val));
    else
        atomicMin((unsigned int*)addr, (unsigned int)__float_as_int(val));
}

__global__ void k_edge1() {
    int idx = blockIdx.x * blockDim.x + threadIdx.x;
    if (idx >= NE * NH) return;
    int j = idx >> 3;
    int h = idx & 7;
    int s = g_ssrc[j];
    int d = g_sdst[j];
    float v = g_el[s * NH + h] + g_er[d * NH + h];
    v = (v > 0.f) ? v : NEG_SLOPE * v;
    g_e[idx] = v;
    atomicMaxFloat(&g_m[d * NH + h], v);
}

__global__ void k_edge2() {
    int idx = blockIdx.x * blockDim.x + threadIdx.x;
    if (idx >= NE * NH) return;
    int j = idx >> 3;
    int h = idx & 7;
    int d = g_sdst[j];
    float ex = expf(g_e[idx] - g_m[d * NH + h]);
    g_e[idx] = ex;
    atomicAdd(&g_s[d * NH + h], ex);
}

// ---------------- CSR aggregation ----------------
template <int D, bool RELU>
__global__ void k_agg(const float* __restrict__ lin,
                      const float* __restrict__ bias,
                      float* __restrict__ out) {
    const int C = NH * D;
    int n = blockIdx.x;
    int tid = threadIdx.x;
    int h = tid / D;
    int beg = g_off[n], end = g_off[n + 1];
    float acc = 0.f;
    __shared__ int s_src[32];
    __shared__ float s_ex[32 * NH];
    for (int base = beg; base < end; base += 32) {
        int cnt = min(32, end - base);
        __syncthreads();
        if (tid < cnt) s_src[tid] = g_ssrc[base + tid];
        for (int i = tid; i < cnt * NH; i += C) s_ex[i] = g_e[base * NH + i];
        __syncthreads();
        for (int jj = 0; jj < cnt; jj++) {
            acc += lin[(size_t)s_src[jj] * C + tid] * s_ex[jj * NH + h];
        }
    }
    float v = (end > beg) ? (acc / g_s[n * NH + h]) : 0.f;
    v += bias[tid];
    if (RELU) v = fmaxf(v, 0.f);
    out[(size_t)n * C + tid] = v;
}

// ---------------- z = mean + noise * exp(log_std), then bf16 hi/lo split ----------------
__global__ void k_z(const float* __restrict__ noise, float* __restrict__ zout) {
    int i = blockIdx.x * blockDim.x + threadIdx.x;
    if (i < NN * ZC) zout[i] = g_mean[i] + noise[i] * expf(g_lstd[i]);
}

__global__ void k_split(const float* __restrict__ z) {
    int i = blockIdx.x * blockDim.x + threadIdx.x;
    if (i >= NPAD * ZC) return;
    if (i < NN * ZC) {
        float v = z[i];
        __nv_bfloat16 h = __float2bfloat16(v);
        g_zhi[i] = h;
        g_zlo[i] = __float2bfloat16(v - __bfloat162float(h));
    } else {
        g_zhi[i] = __float2bfloat16(0.f);
        g_zlo[i] = __float2bfloat16(0.f);
    }
}

// ---------------- adj = sigmoid(z @ z^T) via tcgen05 ----------------
// Per 128x128 tile: Ah/Al/Bh/Bl bf16 tiles (128 rows x 64 bf16 = 128B/row, SW128),
// 12 accumulating cg1 kind::f16 MMAs into one 128-col TMEM accumulator.
// idesc: F32 out, BF16 x BF16, M=128, N=128
#define TC_IDESC 0x8200490u
#define TSM_AH 1024
#define TSM_AL (1024 + 16384)
#define TSM_BH (1024 + 2 * 16384)
#define TSM_BL (1024 + 3 * 16384)
#define TC_SMEM (1024 + 4 * 16384)

__global__ __launch_bounds__(128)
void k_adj_tc(float* __restrict__ adj) {
#if HAS_TCGEN05
    extern __shared__ char smem[];
    uint32_t sb = smem_u32(smem);
    int tid = threadIdx.x, wid = tid >> 5, lid = tid & 31;
    int row0 = blockIdx.y * 128, col0 = blockIdx.x * 128;

    if (wid == 0) {
        TC_ALLOC(sb + 0, 128);
        TC_RELINQ();
    }
    if (tid == 0) MBAR_INIT(sb + 8, 1);

    // load 4 tiles (Ah, Al, Bh, Bl) into SW128-swizzled SMEM (uint4 granularity)
    {
#pragma unroll
        for (int it = 0; it < 8; it++) {
            int idx = it * 128 + tid;
            int r = idx >> 3;
            int c = idx & 7;          // 16B chunk within 128B row
            uint32_t sw = swz128((uint32_t)(r * 128 + c * 16));
            const uint4* pAh = (const uint4*)(g_zhi + (size_t)(row0 + r) * ZC) + c;
            const uint4* pAl = (const uint4*)(g_zlo + (size_t)(row0 + r) * ZC) + c;
            const uint4* pBh = (const uint4*)(g_zhi + (size_t)(col0 + r) * ZC) + c;
            const uint4* pBl = (const uint4*)(g_zlo + (size_t)(col0 + r) * ZC) + c;
            *(uint4*)(smem + TSM_AH + sw) = *pAh;
            *(uint4*)(smem + TSM_AL + sw) = *pAl;
            *(uint4*)(smem + TSM_BH + sw) = *pBh;
            *(uint4*)(smem + TSM_BL + sw) = *pBl;
        }
    }
    __syncthreads();

    uint32_t tmem;
    asm volatile("ld.shared.b32 %0, [%1];" : "=r"(tmem) : "r"(sb + 0));

    if (wid == 0 && elect1()) {
        uint64_t dAh = mk_desc(sb + TSM_AH);
        uint64_t dAl = mk_desc(sb + TSM_AL);
        uint64_t dBh = mk_desc(sb + TSM_BH);
        uint64_t dBl = mk_desc(sb + TSM_BL);
        bool first = true;
#pragma unroll
        for (int p = 0; p < 3; p++) {
            uint64_t da = (p == 2) ? dAl : dAh;
            uint64_t db = (p == 1) ? dBl : dBh;
#pragma unroll
            for (int k = 0; k < 4; k++) {
                mma_f16_ss(tmem, da + k * 2, db + k * 2, TC_IDESC, !first);
                first = false;
            }
        }
        TC_COMMIT(sb + 8);
    }

    MBAR_WAIT(sb + 8, 0);
    TC_FENCE_AFTER();

    // epilogue: each warp reads its 32-lane subpartition (rows wid*32+lid)
    int r = row0 + wid * 32 + lid;
#pragma unroll
    for (int ch = 0; ch < 4; ch++) {
        uint32_t dr[32];
        TC_LD_X32(dr, tmem + ch * 32);
        TC_WAIT_LD();
        if (r < NN) {
            int cbase = col0 + ch * 32;
            float v[32];
#pragma unroll
            for (int j = 0; j < 32; j++)
                v[j] = 1.f / (1.f + __expf(-__uint_as_float(dr[j])));
            float* orow = adj + (size_t)r * NN + cbase;
            if (cbase + 31 < NN) {
#pragma unroll
                for (int q = 0; q < 8; q++)
                    *(float4*)(orow + q * 4) =
                        make_float4(v[q * 4], v[q * 4 + 1], v[q * 4 + 2], v[q * 4 + 3]);
            } else {
#pragma unroll
                for (int j = 0; j < 32; j++)
                    if (cbase + j < NN) orow[j] = v[j];
            }
        }
    }
    TC_FENCE_BEFORE();
    __syncthreads();
    if (tid == 0) MBAR_INVAL(sb + 8);
    __syncthreads();
    if (wid == 0) TC_DEALLOC(tmem, 128);
#endif  // HAS_TCGEN05
}

// ---------------- launcher ----------------
extern "C" void kernel_launch(void* const* d_in, const int* in_sizes, int n_in,
                              void* d_out, int out_size) {
    const float* features = (const float*)d_in[0];
    const int*   src      = (const int*)d_in[1];
    const int*   dst      = (const int*)d_in[2];
    const float* noise    = (const float*)d_in[3];
    const float* W0  = (const float*)d_in[4];
    const float* al0 = (const float*)d_in[5];
    const float* ar0 = (const float*)d_in[6];
    const float* b0  = (const float*)d_in[7];
    const float* W1  = (const float*)d_in[8];
    const float* al1 = (const float*)d_in[9];
    const float* ar1 = (const float*)d_in[10];
    const float* b1  = (const float*)d_in[11];
    const float* W2  = (const float*)d_in[12];
    const float* al2 = (const float*)d_in[13];
    const float* ar2 = (const float*)d_in[14];
    const float* b2  = (const float*)d_in[15];

    float* out = (float*)d_out;
    float* z_out = out;
    float* adj_out = out + (size_t)NN * ZC;

    void* p;
    cudaGetSymbolAddress(&p, g_lin0); float* lin0 = (float*)p;
    cudaGetSymbolAddress(&p, g_gat0); float* gat0 = (float*)p;
    cudaGetSymbolAddress(&p, g_lin1); float* lin1 = (float*)p;
    cudaGetSymbolAddress(&p, g_lin2); float* lin2 = (float*)p;
    cudaGetSymbolAddress(&p, g_mean); float* meanp = (float*)p;
    cudaGetSymbolAddress(&p, g_lstd); float* lstdp = (float*)p;

    // edge sort by dst (shared by all 3 GAT layers)
    k_zero_deg<<<(NN + 255) / 256, 256>>>();
    k_hist<<<(NE + 255) / 256, 256>>>(dst);
    k_scan<<<1, 1024>>>();
    k_scatter<<<(NE + 255) / 256, 256>>>(src, dst);

    const int egrid = (NE * NH + 255) / 256;
    const int ngrid = (NN * NH + 255) / 256;

    // ---- layer 0: 512 -> 256, relu ----
    k_sgemm<<<dim3(HIDC / 64, (NN + 63) / 64), 256>>>(features, W0, lin0, NN, FIN, HIDC);
    k_elr<ND0><<<ngrid, 256>>>(lin0, al0, ar0);
    k_init_ms<<<ngrid, 256>>>();
    k_edge1<<<egrid, 256>>>();
    k_edge2<<<egrid, 256>>>();
    k_agg<ND0, true><<<NN, NH * ND0>>>(lin0, b0, gat0);

    // ---- layer 1 (mean): 256 -> 64 ----
    k_sgemm<<<dim3(ZC / 64, (NN + 63) / 64), 256>>>(gat0, W1, lin1, NN, HIDC, ZC);
    k_elr<ND1><<<ngrid, 256>>>(lin1, al1, ar1);
    k_init_ms<<<ngrid, 256>>>();
    k_edge1<<<egrid, 256>>>();
    k_edge2<<<egrid, 256>>>();
    k_agg<ND1, false><<<NN, NH * ND1>>>(lin1, b1, meanp);

    // ---- layer 2 (log_std): 256 -> 64 ----
    k_sgemm<<<dim3(ZC / 64, (NN + 63) / 64), 256>>>(gat0, W2, lin2, NN, HIDC, ZC);
    k_elr<ND1><<<ngrid, 256>>>(lin2, al2, ar2);
    k_init_ms<<<ngrid, 256>>>();
    k_edge1<<<egrid, 256>>>();
    k_edge2<<<egrid, 256>>>();
    k_agg<ND1, false><<<NN, NH * ND1>>>(lin2, b2, lstdp);

    // ---- z = mean + noise * exp(log_std), split to bf16 hi/lo (padded) ----
    k_z<<<(NN * ZC + 255) / 256, 256>>>(noise, z_out);
    k_split<<<(NPAD * ZC + 255) / 256, 256>>>(z_out);

    // ---- adj = sigmoid(z @ z^T) via tcgen05 ----
    cudaFuncSetAttribute(k_adj_tc, cudaFuncAttributeMaxDynamicSharedMemorySize, TC_SMEM);
    k_adj_tc<<<dim3(NPAD / 128, NPAD / 128), 128, TC_SMEM>>>(adj_out);
}

// round 7
// speedup vs baseline: 2.2634x; 1.0605x over previous
#include <cuda_runtime.h>
#include <cuda_bf16.h>
#include <cstdint>
#include <math.h>

#define NN 10000
#define NPAD 10112           // 79 * 128
#define NE 320000
#define FIN 512
#define HIDC 256
#define ZC 64
#define NH 8
#define ND0 32
#define ND1 8
#define NEG_SLOPE 0.2f

// ---------------- scratch (static device memory; no allocations) ----------------
__device__ float g_lin0[NN * HIDC];
__device__ float g_gat0[NN * HIDC];
__device__ float g_lin1[NN * ZC];
__device__ float g_lin2[NN * ZC];
__device__ float g_mean[NN * ZC];
__device__ float g_lstd[NN * ZC];
__device__ float g_el[NN * NH];
__device__ float g_er[NN * NH];
__device__ float g_el2[NN * NH];
__device__ float g_er2[NN * NH];
__device__ float g_e[NE * NH];        // per-edge scratch (sorted order)
__device__ int   g_deg[NN];
__device__ int   g_off[NN + 1];
__device__ int   g_cur[NN];
__device__ int   g_ssrc[NE];
__device__ __nv_bfloat16 g_zhi[NPAD * ZC];
__device__ __nv_bfloat16 g_zlo[NPAD * ZC];

// Feature gate: tcgen05 only exists on the 'a' targets. The harness also runs a
// plain compute_103 PTX pass; compile an empty body there (runtime picks sm_103a cubin).
#if defined(__CUDA_ARCH_FEAT_SM103_ALL) || defined(__CUDA_ARCH_FEAT_SM100_ALL) || defined(__CUDA_ARCH_FEAT_SM101_ALL)
#define HAS_TCGEN05 1
#else
#define HAS_TCGEN05 0
#endif

// ---------------- PTX helpers ----------------
__device__ __forceinline__ uint32_t smem_u32(const void* p) {
    uint32_t a;
    asm("{ .reg .u64 t; cvta.to.shared.u64 t, %1; cvt.u32.u64 %0, t; }" : "=r"(a) : "l"(p));
    return a;
}
__device__ __forceinline__ uint32_t elect1() {
    uint32_t r;
    asm volatile("{ .reg .pred p; elect.sync _|p, 0xFFFFFFFF; selp.b32 %0,1,0,p; }" : "=r"(r));
    return r;
}
#define MBAR_INIT(mbar, cnt) \
    asm volatile("mbarrier.init.shared.b64 [%0], %1;" :: "r"((uint32_t)(mbar)), "r"((uint32_t)(cnt)) : "memory")
#define MBAR_INVAL(mbar) \
    asm volatile("mbarrier.inval.shared.b64 [%0];" :: "r"((uint32_t)(mbar)) : "memory")
#define MBAR_WAIT(mbar, parity) do {                                           \
    uint32_t _m = (uint32_t)(mbar), _p = (uint32_t)(parity), _d;               \
    asm volatile("{ .reg .pred p; mbarrier.try_wait.parity.acquire.cta.shared::cta.b64 p, [%1], %2; selp.b32 %0,1,0,p; }" \
                 : "=r"(_d) : "r"(_m), "r"(_p) : "memory");                    \
    if (!_d) {                                                                 \
        asm volatile("{ .reg .pred P1; WL%=: mbarrier.try_wait.parity.acquire.cta.shared::cta.b64 P1, [%0], %1, 0x989680; @P1 bra.uni WD%=; bra.uni WL%=; WD%=: }" \
                     :: "r"(_m), "r"(_p) : "memory");                          \
    }                                                                          \
} while (0)

#if HAS_TCGEN05
#define TC_ALLOC(saddr, n) \
    asm volatile("tcgen05.alloc.cta_group::1.sync.aligned.shared::cta.b32 [%0], %1;" \
                 :: "r"((uint32_t)(saddr)), "r"((uint32_t)(n)) : "memory")
#define TC_RELINQ() \
    asm volatile("tcgen05.relinquish_alloc_permit.cta_group::1.sync.aligned;")
#define TC_DEALLOC(tmem, n) \
    asm volatile("tcgen05.dealloc.cta_group::1.sync.aligned.b32 %0, %1;" :: "r"(tmem), "r"((uint32_t)(n)))
#define TC_COMMIT(mbar) \
    asm volatile("tcgen05.commit.cta_group::1.mbarrier::arrive::one.shared::cluster.b64 [%0];" \
                 :: "r"((uint32_t)(mbar)) : "memory")
#define TC_FENCE_AFTER() asm volatile("tcgen05.fence::after_thread_sync;" ::: "memory")
#define TC_FENCE_BEFORE() asm volatile("tcgen05.fence::before_thread_sync;" ::: "memory")
#define TC_WAIT_LD() asm volatile("tcgen05.wait::ld.sync.aligned;" ::: "memory")
#define TC_LD_X32(r, tmem_addr) \
    asm volatile( \
        "tcgen05.ld.sync.aligned.32x32b.x32.b32 " \
        "{%0, %1, %2, %3, %4, %5, %6, %7, " \
        " %8, %9, %10, %11, %12, %13, %14, %15, " \
        " %16, %17, %18, %19, %20, %21, %22, %23, " \
        " %24, %25, %26, %27, %28, %29, %30, %31}, [%32];" \
        : "=r"((r)[0]),  "=r"((r)[1]),  "=r"((r)[2]),  "=r"((r)[3]), \
          "=r"((r)[4]),  "=r"((r)[5]),  "=r"((r)[6]),  "=r"((r)[7]), \
          "=r"((r)[8]),  "=r"((r)[9]),  "=r"((r)[10]), "=r"((r)[11]), \
          "=r"((r)[12]), "=r"((r)[13]), "=r"((r)[14]), "=r"((r)[15]), \
          "=r"((r)[16]), "=r"((r)[17]), "=r"((r)[18]), "=r"((r)[19]), \
          "=r"((r)[20]), "=r"((r)[21]), "=r"((r)[22]), "=r"((r)[23]), \
          "=r"((r)[24]), "=r"((r)[25]), "=r"((r)[26]), "=r"((r)[27]), \
          "=r"((r)[28]), "=r"((r)[29]), "=r"((r)[30]), "=r"((r)[31]) \
        : "r"(tmem_addr))

__device__ __forceinline__ void mma_f16_ss(uint32_t d, uint64_t a, uint64_t b,
                                           uint32_t idesc, bool accum) {
    uint32_t en = accum ? 1u : 0u;
    asm volatile(
        "{\n\t"
        ".reg .pred p;\n\t"
        "setp.ne.u32 p, %5, 0;\n\t"
        "tcgen05.mma.cta_group::1.kind::f16 [%0], %1, %2, %3, {%4, %4, %4, %4}, p;\n\t"
        "}"
        :: "r"(d), "l"(a), "l"(b), "r"(idesc), "r"(0u), "r"(en)
        : "memory");
}
#endif  // HAS_TCGEN05

// SW128 SMEM descriptor (version=1, SBO=64, LBO=1), matches verified examples
__device__ __forceinline__ uint64_t mk_desc(uint32_t saddr) {
    const uint64_t BASE =
        (uint64_t(2) << 61) | (uint64_t(1) << 46) | (uint64_t(64) << 32) | (uint64_t(1) << 16);
    return BASE | ((uint64_t)(saddr >> 4) & 0x3FFF);
}
__device__ __forceinline__ uint32_t swz128(uint32_t off) {
    return off ^ ((off >> 3) & 0x70);
}

// ---------------- counting sort of edges by dst ----------------
__global__ void k_zero_deg() {
    int i = blockIdx.x * blockDim.x + threadIdx.x;
    if (i < NN) g_deg[i] = 0;
}

__global__ void k_hist(const int* __restrict__ dst) {
    int i = blockIdx.x * blockDim.x + threadIdx.x;
    if (i < NE) atomicAdd(&g_deg[dst[i]], 1);
}

__global__ void k_scan() {
    const int CH = 10;
    __shared__ int sh[1024];
    int t = threadIdx.x;
    int base = t * CH;
    int vals[CH];
    int loc = 0;
#pragma unroll
    for (int i = 0; i < CH; i++) {
        int idx = base + i;
        vals[i] = (idx < NN) ? g_deg[idx] : 0;
        loc += vals[i];
    }
    sh[t] = loc;
    __syncthreads();
    for (int off = 1; off < 1024; off <<= 1) {
        int v = (t >= off) ? sh[t - off] : 0;
        __syncthreads();
        sh[t] += v;
        __syncthreads();
    }
    int run = sh[t] - loc;
#pragma unroll
    for (int i = 0; i < CH; i++) {
        int idx = base + i;
        if (idx < NN) {
            g_off[idx] = run;
            g_cur[idx] = run;
            run += vals[i];
        }
    }
    if (t == 0) g_off[NN] = NE;
}

__global__ void k_scatter(const int* __restrict__ src, const int* __restrict__ dst) {
    int e = blockIdx.x * blockDim.x + threadIdx.x;
    if (e < NE) {
        int d = dst[e];
        int pos = atomicAdd(&g_cur[d], 1);
        g_ssrc[pos] = src[e];
    }
}

// ---------------- fp32 tiled GEMM ----------------
__global__ __launch_bounds__(256) void k_sgemm(const float* __restrict__ A,
                                               const float* __restrict__ B,
                                               float* __restrict__ C,
                                               int M, int K, int Nn) {
    __shared__ float As[64 * 32];
    __shared__ float Bs[32 * 64];
    int tid = threadIdx.x;
    int tx = tid & 15, ty = tid >> 4;
    int rowBase = blockIdx.y * 64;
    int colBase = blockIdx.x * 64;
    float acc[4][4] = {};

    for (int kb = 0; kb < K; kb += 32) {
        {
            int r = tid >> 3;
            int c = (tid & 7) << 2;
#pragma unroll
            for (int p = 0; p < 2; p++) {
                int rr = r + p * 32;
                int grow = rowBase + rr;
                float4 v = make_float4(0.f, 0.f, 0.f, 0.f);
                if (grow < M) v = *(const float4*)(A + (size_t)grow * K + kb + c);
                *(float4*)(As + rr * 32 + c) = v;
            }
            int r2 = tid >> 4;
            int c2 = (tid & 15) << 2;
#pragma unroll
            for (int p = 0; p < 2; p++) {
                int rr = r2 + p * 16;
                float4 v = *(const float4*)(B + (size_t)(kb + rr) * Nn + colBase + c2);
                *(float4*)(Bs + rr * 64 + c2) = v;
            }
        }
        __syncthreads();
#pragma unroll
        for (int kk = 0; kk < 32; kk++) {
            float4 b0 = *(const float4*)(Bs + kk * 64 + tx * 4);
            float a0 = As[(ty * 4 + 0) * 32 + kk];
            float a1 = As[(ty * 4 + 1) * 32 + kk];
            float a2 = As[(ty * 4 + 2) * 32 + kk];
            float a3 = As[(ty * 4 + 3) * 32 + kk];
            acc[0][0] += a0 * b0.x; acc[0][1] += a0 * b0.y; acc[0][2] += a0 * b0.z; acc[0][3] += a0 * b0.w;
            acc[1][0] += a1 * b0.x; acc[1][1] += a1 * b0.y; acc[1][2] += a1 * b0.z; acc[1][3] += a1 * b0.w;
            acc[2][0] += a2 * b0.x; acc[2][1] += a2 * b0.y; acc[2][2] += a2 * b0.z; acc[2][3] += a2 * b0.w;
            acc[3][0] += a3 * b0.x; acc[3][1] += a3 * b0.y; acc[3][2] += a3 * b0.z; acc[3][3] += a3 * b0.w;
        }
        __syncthreads();
    }
#pragma unroll
    for (int i = 0; i < 4; i++) {
        int grow = rowBase + ty * 4 + i;
        if (grow < M) {
            *(float4*)(C + (size_t)grow * Nn + colBase + tx * 4) =
                make_float4(acc[i][0], acc[i][1], acc[i][2], acc[i][3]);
        }
    }
}

// ---------------- el/er ----------------
template <int D>
__global__ void k_elr(const float* __restrict__ lin,
                      const float* __restrict__ al,
                      const float* __restrict__ ar,
                      float* __restrict__ elo, float* __restrict__ ero) {
    int i = blockIdx.x * blockDim.x + threadIdx.x;
    if (i >= NN * NH) return;
    int n = i / NH, h = i % NH;
    float el = 0.f, er = 0.f;
#pragma unroll
    for (int d = 0; d < D; d++) {
        float v = lin[n * (NH * D) + h * D + d];
        el += v * al[h * D + d];
        er += v * ar[h * D + d];
    }
    elo[i] = el;
    ero[i] = er;
}

// ---------------- fused per-node GAT: e, max, exp, sum, aggregate ----------------
// One block per dst node, C = NH*D threads. Edges are dst-sorted so the block's
// edge range is contiguous; per-head max/sum are shared-memory reductions.
template <int D, bool RELU>
__global__ void k_gat_fused(const float* __restrict__ lin,
                            const float* __restrict__ elp,
                            const float* __restrict__ erp,
                            const float* __restrict__ bias,
                            float* __restrict__ out) {
    const int C = NH * D;
    int n = blockIdx.x;
    int tid = threadIdx.x;     // 0..C-1
    int beg = g_off[n], end = g_off[n + 1];
    __shared__ int   s_m[NH];       // float-as-int max
    __shared__ float s_sum[NH];
    __shared__ int   s_src[32];
    __shared__ float s_ex[32 * NH];
    if (tid < NH) { s_m[tid] = __float_as_int(-INFINITY); s_sum[tid] = 0.f; }
    __syncthreads();

    // pass 1: e = leaky_relu(el[src]+er[n]); store; block max per head
    {
        int h = tid & 7;
        float ern = erp[n * NH + h];
        for (int j0 = beg + (tid >> 3); j0 < end; j0 += C / NH) {
            int s = g_ssrc[j0];
            float v = elp[s * NH + h] + ern;
            v = (v > 0.f) ? v : NEG_SLOPE * v;
            g_e[(size_t)j0 * NH + h] = v;
            if (v >= 0.f)
                atomicMax(&s_m[h], __float_as_int(v));
            else
                atomicMin((unsigned int*)&s_m[h], (unsigned int)__float_as_int(v));
        }
    }
    __syncthreads();

    // pass 2: exp + sum + aggregate in 32-edge chunks
    float acc = 0.f;
    int hA = tid / D;
    for (int base = beg; base < end; base += 32) {
        int cnt = min(32, end - base);
        __syncthreads();
        if (tid < cnt) s_src[tid] = g_ssrc[base + tid];
        for (int i = tid; i < cnt * NH; i += C) {
            float ex = __expf(g_e[(size_t)base * NH + i] - __int_as_float(s_m[i & 7]));
            s_ex[i] = ex;
            atomicAdd(&s_sum[i & 7], ex);
        }
        __syncthreads();
        for (int jj = 0; jj < cnt; jj++)
            acc += lin[(size_t)s_src[jj] * C + tid] * s_ex[jj * NH + hA];
    }
    float v = (end > beg) ? acc / s_sum[hA] : 0.f;
    v += bias[tid];
    if (RELU) v = fmaxf(v, 0.f);
    out[(size_t)n * C + tid] = v;
}

// ---------------- z = mean + noise * exp(log_std), then bf16 hi/lo split ----------------
__global__ void k_z(const float* __restrict__ noise, float* __restrict__ zout) {
    int i = blockIdx.x * blockDim.x + threadIdx.x;
    if (i < NN * ZC) zout[i] = g_mean[i] + noise[i] * expf(g_lstd[i]);
}

__global__ void k_split(const float* __restrict__ z) {
    int i = blockIdx.x * blockDim.x + threadIdx.x;
    if (i >= NPAD * ZC) return;
    if (i < NN * ZC) {
        float v = z[i];
        __nv_bfloat16 h = __float2bfloat16(v);
        g_zhi[i] = h;
        g_zlo[i] = __float2bfloat16(v - __bfloat162float(h));
    } else {
        g_zhi[i] = __float2bfloat16(0.f);
        g_zlo[i] = __float2bfloat16(0.f);
    }
}

// ---------------- adj = sigmoid(z @ z^T) via tcgen05 ----------------
#define TC_IDESC 0x8200490u
#define TSM_AH 1024
#define TSM_AL (1024 + 16384)
#define TSM_BH (1024 + 2 * 16384)
#define TSM_BL (1024 + 3 * 16384)
#define TC_SMEM (1024 + 4 * 16384)

__global__ __launch_bounds__(128)
void k_adj_tc(float* __restrict__ adj) {
#if HAS_TCGEN05
    extern __shared__ char smem[];
    uint32_t sb = smem_u32(smem);
    int tid = threadIdx.x, wid = tid >> 5, lid = tid & 31;
    int row0 = blockIdx.y * 128, col0 = blockIdx.x * 128;

    if (wid == 0) {
        TC_ALLOC(sb + 0, 128);
        TC_RELINQ();
    }
    if (tid == 0) MBAR_INIT(sb + 8, 1);

    // load 4 tiles (Ah, Al, Bh, Bl) into SW128-swizzled SMEM (uint4 granularity)
    {
#pragma unroll
        for (int it = 0; it < 8; it++) {
            int idx = it * 128 + tid;
            int r = idx >> 3;
            int c = idx & 7;          // 16B chunk within 128B row
            uint32_t sw = swz128((uint32_t)(r * 128 + c * 16));
            const uint4* pAh = (const uint4*)(g_zhi + (size_t)(row0 + r) * ZC) + c;
            const uint4* pAl = (const uint4*)(g_zlo + (size_t)(row0 + r) * ZC) + c;
            const uint4* pBh = (const uint4*)(g_zhi + (size_t)(col0 + r) * ZC) + c;
            const uint4* pBl = (const uint4*)(g_zlo + (size_t)(col0 + r) * ZC) + c;
            *(uint4*)(smem + TSM_AH + sw) = *pAh;
            *(uint4*)(smem + TSM_AL + sw) = *pAl;
            *(uint4*)(smem + TSM_BH + sw) = *pBh;
            *(uint4*)(smem + TSM_BL + sw) = *pBl;
        }
    }
    __syncthreads();

    uint32_t tmem;
    asm volatile("ld.shared.b32 %0, [%1];" : "=r"(tmem) : "r"(sb + 0));

    if (wid == 0 && elect1()) {
        uint64_t dAh = mk_desc(sb + TSM_AH);
        uint64_t dAl = mk_desc(sb + TSM_AL);
        uint64_t dBh = mk_desc(sb + TSM_BH);
        uint64_t dBl = mk_desc(sb + TSM_BL);
        bool first = true;
#pragma unroll
        for (int p = 0; p < 3; p++) {
            uint64_t da = (p == 2) ? dAl : dAh;
            uint64_t db = (p == 1) ? dBl : dBh;
#pragma unroll
            for (int k = 0; k < 4; k++) {
                mma_f16_ss(tmem, da + k * 2, db + k * 2, TC_IDESC, !first);
                first = false;
            }
        }
        TC_COMMIT(sb + 8);
    }

    MBAR_WAIT(sb + 8, 0);
    TC_FENCE_AFTER();

    // epilogue: each warp reads its 32-lane subpartition (rows wid*32+lid)
    int r = row0 + wid * 32 + lid;
#pragma unroll
    for (int ch = 0; ch < 4; ch++) {
        uint32_t dr[32];
        TC_LD_X32(dr, tmem + ch * 32);
        TC_WAIT_LD();
        if (r < NN) {
            int cbase = col0 + ch * 32;
            float v[32];
#pragma unroll
            for (int j = 0; j < 32; j++)
                v[j] = 1.f / (1.f + __expf(-__uint_as_float(dr[j])));
            float* orow = adj + (size_t)r * NN + cbase;
            if (cbase + 31 < NN) {
#pragma unroll
                for (int q = 0; q < 8; q++)
                    *(float4*)(orow + q * 4) =
                        make_float4(v[q * 4], v[q * 4 + 1], v[q * 4 + 2], v[q * 4 + 3]);
            } else {
#pragma unroll
                for (int j = 0; j < 32; j++)
                    if (cbase + j < NN) orow[j] = v[j];
            }
        }
    }
    TC_FENCE_BEFORE();
    __syncthreads();
    if (tid == 0) MBAR_INVAL(sb + 8);
    __syncthreads();
    if (wid == 0) TC_DEALLOC(tmem, 128);
#endif  // HAS_TCGEN05
}

// ---------------- launcher ----------------
extern "C" void kernel_launch(void* const* d_in, const int* in_sizes, int n_in,
                              void* d_out, int out_size) {
    const float* features = (const float*)d_in[0];
    const int*   src      = (const int*)d_in[1];
    const int*   dst      = (const int*)d_in[2];
    const float* noise    = (const float*)d_in[3];
    const float* W0  = (const float*)d_in[4];
    const float* al0 = (const float*)d_in[5];
    const float* ar0 = (const float*)d_in[6];
    const float* b0  = (const float*)d_in[7];
    const float* W1  = (const float*)d_in[8];
    const float* al1 = (const float*)d_in[9];
    const float* ar1 = (const float*)d_in[10];
    const float* b1  = (const float*)d_in[11];
    const float* W2  = (const float*)d_in[12];
    const float* al2 = (const float*)d_in[13];
    const float* ar2 = (const float*)d_in[14];
    const float* b2  = (const float*)d_in[15];

    float* out = (float*)d_out;
    float* z_out = out;
    float* adj_out = out + (size_t)NN * ZC;

    void* p;
    cudaGetSymbolAddress(&p, g_lin0); float* lin0 = (float*)p;
    cudaGetSymbolAddress(&p, g_gat0); float* gat0 = (float*)p;
    cudaGetSymbolAddress(&p, g_lin1); float* lin1 = (float*)p;
    cudaGetSymbolAddress(&p, g_lin2); float* lin2 = (float*)p;
    cudaGetSymbolAddress(&p, g_mean); float* meanp = (float*)p;
    cudaGetSymbolAddress(&p, g_lstd); float* lstdp = (float*)p;
    cudaGetSymbolAddress(&p, g_el);  float* el = (float*)p;
    cudaGetSymbolAddress(&p, g_er);  float* er = (float*)p;
    cudaGetSymbolAddress(&p, g_el2); float* el2 = (float*)p;
    cudaGetSymbolAddress(&p, g_er2); float* er2 = (float*)p;

    // edge sort by dst (shared by all 3 GAT layers)
    k_zero_deg<<<(NN + 255) / 256, 256>>>();
    k_hist<<<(NE + 255) / 256, 256>>>(dst);
    k_scan<<<1, 1024>>>();
    k_scatter<<<(NE + 255) / 256, 256>>>(src, dst);

    const int ngrid = (NN * NH + 255) / 256;

    // ---- layer 0: 512 -> 256, relu ----
    k_sgemm<<<dim3(HIDC / 64, (NN + 63) / 64), 256>>>(features, W0, lin0, NN, FIN, HIDC);
    k_elr<ND0><<<ngrid, 256>>>(lin0, al0, ar0, el, er);
    k_gat_fused<ND0, true><<<NN, HIDC>>>(lin0, el, er, b0, gat0);

    // ---- layers 1 & 2: 256 -> 64 ----
    k_sgemm<<<dim3(ZC / 64, (NN + 63) / 64), 256>>>(gat0, W1, lin1, NN, HIDC, ZC);
    k_sgemm<<<dim3(ZC / 64, (NN + 63) / 64), 256>>>(gat0, W2, lin2, NN, HIDC, ZC);
    k_elr<ND1><<<ngrid, 256>>>(lin1, al1, ar1, el, er);
    k_elr<ND1><<<ngrid, 256>>>(lin2, al2, ar2, el2, er2);
    k_gat_fused<ND1, false><<<NN, ZC>>>(lin1, el, er, b1, meanp);
    k_gat_fused<ND1, false><<<NN, ZC>>>(lin2, el2, er2, b2, lstdp);

    // ---- z = mean + noise * exp(log_std), split to bf16 hi/lo (padded) ----
    k_z<<<(NN * ZC + 255) / 256, 256>>>(noise, z_out);
    k_split<<<(NPAD * ZC + 255) / 256, 256>>>(z_out);

    // ---- adj = sigmoid(z @ z^T) via tcgen05 ----
    cudaFuncSetAttribute(k_adj_tc, cudaFuncAttributeMaxDynamicSharedMemorySize, TC_SMEM);
    k_adj_tc<<<dim3(NPAD / 128, NPAD / 128), 128, TC_SMEM>>>(adj_out);
}